// round 5
// baseline (speedup 1.0000x reference)
#include <cuda_runtime.h>
#include <cuda_fp16.h>
#include <cstdint>

// Problem shape (fixed by the dataset): q,k,v [4, 16, 2048, 64] fp32.
#define BATCH 4
#define HEADS 16
#define SEQ   2048
#define HDIM  64

#define QT 128           // q rows per CTA
#define KT 64            // keys per smem tile
#define NWARP 4          // 128 threads; each warp owns 32 q rows (two m16 blocks)

// Smem layouts (element = uint32 = half2):
//  Ks[key][pair d/2]   : stride 36 u32  (36 mod 32 == 4 -> banks 4g+t, conflict-free B loads)
//  Vp[keypair][d]      : stride 72 u32  (72 mod 32 == 8 -> banks 8t+g, conflict-free B loads)
#define KS_STRIDE 36
#define VP_STRIDE 72

static __device__ __forceinline__ float fast_ex2(float x) {
    float r;
    asm("ex2.approx.f32 %0, %1;" : "=f"(r) : "f"(x));
    return r;
}

static __device__ __forceinline__ uint32_t f2h2(float lo, float hi) {
    __half2 h = __floats2half2_rn(lo, hi);
    return *(uint32_t*)&h;
}

// D(16x8,f32) += A(16x16,f16) * B(16x8,f16), row.col
static __device__ __forceinline__ void mma_f16(float d[4],
                                               uint32_t a0, uint32_t a1,
                                               uint32_t a2, uint32_t a3,
                                               uint32_t b0, uint32_t b1) {
    asm("mma.sync.aligned.m16n8k16.row.col.f32.f16.f16.f32 "
        "{%0,%1,%2,%3}, {%4,%5,%6,%7}, {%8,%9}, {%0,%1,%2,%3};\n"
        : "+f"(d[0]), "+f"(d[1]), "+f"(d[2]), "+f"(d[3])
        : "r"(a0), "r"(a1), "r"(a2), "r"(a3), "r"(b0), "r"(b1));
}

__global__ void __launch_bounds__(NWARP * 32)
attn_f16_m32_kernel(const float* __restrict__ q,
                    const float* __restrict__ k,
                    const float* __restrict__ v,
                    float* __restrict__ out)
{
    __shared__ uint32_t Ks[KT][KS_STRIDE];        // half2: K[key][2d, 2d+1]
    __shared__ uint32_t Vp[KT / 2][VP_STRIDE];    // half2: {V[2p][d], V[2p+1][d]}

    const int bh    = blockIdx.y;            // 0..63
    const int qtile = blockIdx.x;            // 0..15
    const int tid   = threadIdx.x;
    const int wid   = tid >> 5;
    const int lane  = tid & 31;
    const int g     = lane >> 2;             // groupID (row within m16)
    const int t     = lane & 3;              // threadID in group

    const size_t base = (size_t)bh * SEQ * HDIM;
    const float* Qp = q + base + (size_t)qtile * QT * HDIM;
    const float* Kp = k + base;
    const float* Vg = v + base;
    float*       Op = out + base + (size_t)qtile * QT * HDIM;

    // ---- Load Q fragments as fp16: two m16 row-blocks per warp ----
    // Prescale by softmax scale (1/8) * log2(e) so softmax uses ex2 directly.
    const float qscale = 0.125f * 1.4426950408889634f;
    uint32_t a[2][4][4];   // [half][kc][frag]
    #pragma unroll
    for (int h = 0; h < 2; h++) {
        const int r0 = wid * 32 + h * 16 + g;
        #pragma unroll
        for (int kc = 0; kc < 4; kc++) {
            const float* q0 = Qp + (size_t)r0 * HDIM + kc * 16;
            const float* q1 = Qp + (size_t)(r0 + 8) * HDIM + kc * 16;
            a[h][kc][0] = f2h2(q0[2*t    ] * qscale, q0[2*t + 1] * qscale);
            a[h][kc][1] = f2h2(q1[2*t    ] * qscale, q1[2*t + 1] * qscale);
            a[h][kc][2] = f2h2(q0[2*t + 8] * qscale, q0[2*t + 9] * qscale);
            a[h][kc][3] = f2h2(q1[2*t + 8] * qscale, q1[2*t + 9] * qscale);
        }
    }

    float o[2][8][4];
    #pragma unroll
    for (int h = 0; h < 2; h++)
        #pragma unroll
        for (int n = 0; n < 8; n++) { o[h][n][0] = o[h][n][1] = o[h][n][2] = o[h][n][3] = 0.f; }

    float m[2][2] = {{-1e30f, -1e30f}, {-1e30f, -1e30f}};   // [half][row 0/8]
    float l[2][2] = {{0.f, 0.f}, {0.f, 0.f}};

    for (int kt = 0; kt < SEQ; kt += KT) {
        __syncthreads();
        // ---- Stage K tile: fp16 [key][d] pairs; 64x16 float4 / 128 thr = 8 iters ----
        #pragma unroll
        for (int i = 0; i < 8; i++) {
            int idx = tid + i * 128;          // 0..1023
            int row = idx >> 4;               // key 0..63
            int c   = (idx & 15) << 2;        // d 0..60 step 4
            float4 kv = *(const float4*)(Kp + (size_t)(kt + row) * HDIM + c);
            uint2 hp;
            hp.x = f2h2(kv.x, kv.y);
            hp.y = f2h2(kv.z, kv.w);
            *(uint2*)&Ks[row][c >> 1] = hp;   // 8B aligned
        }
        // ---- Stage V tile pre-paired: Vp[p][d] = {V[2p][d], V[2p+1][d]} ----
        #pragma unroll
        for (int i = 0; i < 4; i++) {
            int idx = tid + i * 128;          // 0..511
            int p   = idx >> 4;               // key pair 0..31
            int c   = (idx & 15) << 2;        // d 0..60 step 4
            float4 v0 = *(const float4*)(Vg + (size_t)(kt + 2*p    ) * HDIM + c);
            float4 v1 = *(const float4*)(Vg + (size_t)(kt + 2*p + 1) * HDIM + c);
            uint4 hp;
            hp.x = f2h2(v0.x, v1.x);
            hp.y = f2h2(v0.y, v1.y);
            hp.z = f2h2(v0.z, v1.z);
            hp.w = f2h2(v0.w, v1.w);
            *(uint4*)&Vp[p][c] = hp;          // 16B aligned
        }
        __syncthreads();

        // ---- S = (Q*scale) @ K^T   [32 x 64 per warp]; B-frags shared across halves ----
        float s[2][8][4];
        #pragma unroll
        for (int h = 0; h < 2; h++)
            #pragma unroll
            for (int n = 0; n < 8; n++) { s[h][n][0] = s[h][n][1] = s[h][n][2] = s[h][n][3] = 0.f; }

        #pragma unroll
        for (int kc = 0; kc < 4; kc++) {
            #pragma unroll
            for (int n = 0; n < 8; n++) {
                uint32_t b0 = Ks[n * 8 + g][8 * kc + t];
                uint32_t b1 = Ks[n * 8 + g][8 * kc + t + 4];
                mma_f16(s[0][n], a[0][kc][0], a[0][kc][1], a[0][kc][2], a[0][kc][3], b0, b1);
                mma_f16(s[1][n], a[1][kc][0], a[1][kc][1], a[1][kc][2], a[1][kc][3], b0, b1);
            }
        }

        // ---- Online softmax per half (rows g and g+8 per thread) ----
        float al[2][2];
        #pragma unroll
        for (int h = 0; h < 2; h++) {
            float mx0 = -1e30f, mx1 = -1e30f;
            #pragma unroll
            for (int n = 0; n < 8; n++) {
                mx0 = fmaxf(mx0, fmaxf(s[h][n][0], s[h][n][1]));
                mx1 = fmaxf(mx1, fmaxf(s[h][n][2], s[h][n][3]));
            }
            mx0 = fmaxf(mx0, __shfl_xor_sync(0xffffffffu, mx0, 1));
            mx0 = fmaxf(mx0, __shfl_xor_sync(0xffffffffu, mx0, 2));
            mx1 = fmaxf(mx1, __shfl_xor_sync(0xffffffffu, mx1, 1));
            mx1 = fmaxf(mx1, __shfl_xor_sync(0xffffffffu, mx1, 2));

            float nm0 = fmaxf(m[h][0], mx0);
            float nm1 = fmaxf(m[h][1], mx1);
            al[h][0] = fast_ex2(m[h][0] - nm0);
            al[h][1] = fast_ex2(m[h][1] - nm1);
            m[h][0] = nm0; m[h][1] = nm1;

            float rs0 = 0.f, rs1 = 0.f;
            #pragma unroll
            for (int n = 0; n < 8; n++) {
                s[h][n][0] = fast_ex2(s[h][n][0] - nm0);
                s[h][n][1] = fast_ex2(s[h][n][1] - nm0);
                s[h][n][2] = fast_ex2(s[h][n][2] - nm1);
                s[h][n][3] = fast_ex2(s[h][n][3] - nm1);
                rs0 += s[h][n][0] + s[h][n][1];
                rs1 += s[h][n][2] + s[h][n][3];
            }
            rs0 += __shfl_xor_sync(0xffffffffu, rs0, 1);
            rs0 += __shfl_xor_sync(0xffffffffu, rs0, 2);
            rs1 += __shfl_xor_sync(0xffffffffu, rs1, 1);
            rs1 += __shfl_xor_sync(0xffffffffu, rs1, 2);
            l[h][0] = l[h][0] * al[h][0] + rs0;
            l[h][1] = l[h][1] * al[h][1] + rs1;

            #pragma unroll
            for (int n = 0; n < 8; n++) {
                o[h][n][0] *= al[h][0]; o[h][n][1] *= al[h][0];
                o[h][n][2] *= al[h][1]; o[h][n][3] *= al[h][1];
            }
        }

        // ---- O += P @ V  (C-frag maps directly onto A-frag; V B-frags shared) ----
        #pragma unroll
        for (int kc = 0; kc < 4; kc++) {     // keys 16kc .. 16kc+15
            uint32_t pa[2][4];
            #pragma unroll
            for (int h = 0; h < 2; h++) {
                pa[h][0] = f2h2(s[h][2*kc    ][0], s[h][2*kc    ][1]);
                pa[h][1] = f2h2(s[h][2*kc    ][2], s[h][2*kc    ][3]);
                pa[h][2] = f2h2(s[h][2*kc + 1][0], s[h][2*kc + 1][1]);
                pa[h][3] = f2h2(s[h][2*kc + 1][2], s[h][2*kc + 1][3]);
            }
            #pragma unroll
            for (int nn = 0; nn < 8; nn++) {
                uint32_t b0 = Vp[8 * kc + t    ][nn * 8 + g];
                uint32_t b1 = Vp[8 * kc + t + 4][nn * 8 + g];
                mma_f16(o[0][nn], pa[0][0], pa[0][1], pa[0][2], pa[0][3], b0, b1);
                mma_f16(o[1][nn], pa[1][0], pa[1][1], pa[1][2], pa[1][3], b0, b1);
            }
        }
    }

    // ---- Epilogue: normalize and store 32 rows ----
    #pragma unroll
    for (int h = 0; h < 2; h++) {
        const float il0 = 1.0f / l[h][0];
        const float il1 = 1.0f / l[h][1];
        const int r0 = wid * 32 + h * 16 + g;
        #pragma unroll
        for (int n = 0; n < 8; n++) {
            float2 w0 = make_float2(o[h][n][0] * il0, o[h][n][1] * il0);
            float2 w1 = make_float2(o[h][n][2] * il1, o[h][n][3] * il1);
            *(float2*)(Op + (size_t)(r0    ) * HDIM + n * 8 + 2 * t) = w0;
            *(float2*)(Op + (size_t)(r0 + 8) * HDIM + n * 8 + 2 * t) = w1;
        }
    }
}

extern "C" void kernel_launch(void* const* d_in, const int* in_sizes, int n_in,
                              void* d_out, int out_size)
{
    (void)in_sizes; (void)n_in; (void)out_size;
    const float* q = (const float*)d_in[0];
    const float* k = (const float*)d_in[1];
    const float* v = (const float*)d_in[2];
    float* out = (float*)d_out;

    dim3 grid(SEQ / QT, BATCH * HEADS);   // (16, 64)
    dim3 block(NWARP * 32);               // 128
    attn_f16_m32_kernel<<<grid, block>>>(q, k, v, out);
}